// round 11
// baseline (speedup 1.0000x reference)
#include <cuda_runtime.h>
#include <math.h>

#define T_SAMPLES 128
#define HID 16
#define HPAIRS (HID / 2)

typedef unsigned long long u64;

#define LOG2E 1.4426950408889634f

// ---- packed f32x2 helpers (sm_100+; emits FFMA2 in SASS) ----
__device__ __forceinline__ u64 pack2(float lo, float hi) {
    u64 r; asm("mov.b64 %0, {%1,%2};" : "=l"(r) : "f"(lo), "f"(hi)); return r;
}
__device__ __forceinline__ void unpack2(u64 v, float& lo, float& hi) {
    asm("mov.b64 {%0,%1}, %2;" : "=f"(lo), "=f"(hi) : "l"(v));
}
__device__ __forceinline__ u64 fma2(u64 a, u64 b, u64 c) {
    u64 r; asm("fma.rn.f32x2 %0, %1, %2, %3;" : "=l"(r) : "l"(a), "l"(b), "l"(c));
    return r;
}
__device__ __forceinline__ u64 relu2(u64 v) {
    float lo, hi;
    unpack2(v, lo, hi);
    lo = fmaxf(lo, 0.0f);     // FMNMX -> alu pipe
    hi = fmaxf(hi, 0.0f);
    return pack2(lo, hi);
}
__device__ __forceinline__ float ex2(float x) {
    float r; asm("ex2.approx.f32 %0, %1;" : "=f"(r) : "f"(x)); return r;
}
__device__ __forceinline__ float lg2(float x) {
    float r; asm("lg2.approx.f32 %0, %1;" : "=f"(r) : "f"(x)); return r;
}
__device__ __forceinline__ float rcp(float x) {
    float r; asm("rcp.approx.f32 %0, %1;" : "=f"(r) : "f"(x)); return r;
}

__global__ void __launch_bounds__(128, 4)
nerf_render_kernel(const float* __restrict__ o,
                   const float* __restrict__ d,
                   const float* __restrict__ tnear,
                   const float* __restrict__ tfar,
                   const float* __restrict__ noise,
                   const float* __restrict__ W1,      // (3,16)
                   const float* __restrict__ b1,      // (16)
                   const float* __restrict__ w_sigma, // (16,1)
                   const float* __restrict__ W_rgb,   // (16,3)
                   float* __restrict__ out,           // (N,5)
                   int N)
{
    // output-layer weights in smem: per pair p, [ws, wr0, wr1, wr2] packed f32x2.
    // 8 pairs * 4 * 8B = 256 B, 32B-aligned rows -> two LDS.128 per pair, broadcast.
    __shared__ __align__(16) u64 swt[HPAIRS][4];

    const int tid = threadIdx.x;
    if (tid < HPAIRS * 4) {
        const int p = tid >> 2;
        const int k = tid & 3;
        const int j = 2 * p;
        u64 v;
        if (k == 0)      v = pack2(__ldg(&w_sigma[j]),        __ldg(&w_sigma[j + 1]));
        else if (k == 1) v = pack2(__ldg(&W_rgb[j * 3 + 0]),  __ldg(&W_rgb[(j + 1) * 3 + 0]));
        else if (k == 2) v = pack2(__ldg(&W_rgb[j * 3 + 1]),  __ldg(&W_rgb[(j + 1) * 3 + 1]));
        else             v = pack2(__ldg(&W_rgb[j * 3 + 2]),  __ldg(&W_rgb[(j + 1) * 3 + 2]));
        swt[p][k] = v;
    }
    __syncthreads();

    const int ray = blockIdx.x * blockDim.x + tid;
    if (ray >= N) return;

    // ---- per-ray geometry ----
    const float ox = o[3 * ray + 0], oy = o[3 * ray + 1], oz = o[3 * ray + 2];
    const float dx = d[3 * ray + 0], dy = d[3 * ray + 1], dz = d[3 * ray + 2];
    const float dn = sqrtf(dx * dx + dy * dy + dz * dz);
    const float tn = tnear[ray];
    const float tf = tfar[ray];
    const float step = (tf - tn) * (1.0f / (float)T_SAMPLES);

    // ---- fold ray into layer-1: pre_j(t) = A_j + t * B_j ----
    u64 Ap[HPAIRS], Bp[HPAIRS];
#pragma unroll
    for (int p = 0; p < HPAIRS; p++) {
        const int j = 2 * p;
        const float w1x0 = __ldg(&W1[0 * HID + j]), w1x1 = __ldg(&W1[0 * HID + j + 1]);
        const float w1y0 = __ldg(&W1[1 * HID + j]), w1y1 = __ldg(&W1[1 * HID + j + 1]);
        const float w1z0 = __ldg(&W1[2 * HID + j]), w1z1 = __ldg(&W1[2 * HID + j + 1]);
        const float A0 = fmaf(ox, w1x0, fmaf(oy, w1y0, fmaf(oz, w1z0, __ldg(&b1[j]))));
        const float A1 = fmaf(ox, w1x1, fmaf(oy, w1y1, fmaf(oz, w1z1, __ldg(&b1[j + 1]))));
        const float B0 = fmaf(dx, w1x0, fmaf(dy, w1y0, dz * w1z0));
        const float B1 = fmaf(dx, w1x1, fmaf(dy, w1y1, dz * w1z1));
        Ap[p] = pack2(A0, A1);
        Bp[p] = pack2(B0, B1);
    }

    float ts_prev = fmaf(step, noise[ray], tn);

    float Ttr = 1.0f;
    float c0 = 0.f, c1 = 0.f, c2 = 0.f, dep = 0.f, alp = 0.f;

    // two samples per iteration, MLPs manually interleaved (structural ILP-2)
#pragma unroll 2
    for (int t0 = 1; t0 < T_SAMPLES; t0 += 2) {
        const float ua = __ldg(&noise[(size_t)t0 * N + ray]);
        const float ts_a = fmaf(step, (float)t0 + ua, tn);
        float ts_b;
        if (t0 + 1 < T_SAMPLES) {
            const float ub = __ldg(&noise[(size_t)(t0 + 1) * N + ray]);
            ts_b = fmaf(step, (float)(t0 + 1) + ub, tn);
        } else {
            ts_b = tf;
        }

        const float nk_a = (ts_prev - ts_a) * dn;
        const float nk_b = (ts_a - ts_b) * dn;

        const u64 tpa = pack2(ts_prev, ts_prev);
        const u64 tpb = pack2(ts_a, ts_a);

        u64 sa = 0ull, a0 = 0ull, a1 = 0ull, a2 = 0ull;
        u64 sb = 0ull, b0 = 0ull, b1v = 0ull, b2 = 0ull;
#pragma unroll
        for (int p = 0; p < HPAIRS; p++) {
            // two LDS.128 (broadcast) fetch ws/wr0 and wr1/wr2 for this pair
            const ulonglong2 w01 = *reinterpret_cast<const ulonglong2*>(&swt[p][0]);
            const ulonglong2 w23 = *reinterpret_cast<const ulonglong2*>(&swt[p][2]);

            u64 ha = fma2(tpa, Bp[p], Ap[p]);
            u64 hb = fma2(tpb, Bp[p], Ap[p]);
            ha = relu2(ha);
            hb = relu2(hb);
            sa  = fma2(ha, w01.x, sa);
            sb  = fma2(hb, w01.x, sb);
            a0  = fma2(ha, w01.y, a0);
            b0  = fma2(hb, w01.y, b0);
            a1  = fma2(ha, w23.x, a1);
            b1v = fma2(hb, w23.x, b1v);
            a2  = fma2(ha, w23.y, a2);
            b2  = fma2(hb, w23.y, b2);
        }

        float xl, xh;
        unpack2(sa, xl, xh);  const float accs_a = xl + xh;
        unpack2(sb, xl, xh);  const float accs_b = xl + xh;
        unpack2(a0, xl, xh);  const float r0a = xl + xh;
        unpack2(a1, xl, xh);  const float r1a = xl + xh;
        unpack2(a2, xl, xh);  const float r2a = xl + xh;
        unpack2(b0, xl, xh);  const float r0b = xl + xh;
        unpack2(b1v, xl, xh); const float r1b = xl + xh;
        unpack2(b2, xl, xh);  const float r2b = xl + xh;

        // fused softplus+exp:  e = 2^( -k * log2(1 + 2^(a*log2e)) )
        const float la = lg2(1.0f + ex2(accs_a * LOG2E));
        const float lb = lg2(1.0f + ex2(accs_b * LOG2E));
        const float ea = ex2(nk_a * la);
        const float eb = ex2(nk_b * lb);

        const float s0a = rcp(1.0f + ex2(-r0a * LOG2E));
        const float s1a = rcp(1.0f + ex2(-r1a * LOG2E));
        const float s2a = rcp(1.0f + ex2(-r2a * LOG2E));
        const float s0b = rcp(1.0f + ex2(-r0b * LOG2E));
        const float s1b = rcp(1.0f + ex2(-r1b * LOG2E));
        const float s2b = rcp(1.0f + ex2(-r2b * LOG2E));

        const float wa = Ttr * (1.0f - ea);
        const float Ttr_a = Ttr * ea;
        const float wb = Ttr_a * (1.0f - eb);
        Ttr = Ttr_a * eb;

        c0  = fmaf(wa, s0a, fmaf(wb, s0b, c0));
        c1  = fmaf(wa, s1a, fmaf(wb, s1b, c1));
        c2  = fmaf(wa, s2a, fmaf(wb, s2b, c2));
        dep = fmaf(wa, ts_prev, fmaf(wb, ts_a, dep));
        alp += wa + wb;

        ts_prev = ts_b;
    }

    out[5 * ray + 0] = c0;
    out[5 * ray + 1] = c1;
    out[5 * ray + 2] = c2;
    out[5 * ray + 3] = dep;
    out[5 * ray + 4] = alp;
}

extern "C" void kernel_launch(void* const* d_in, const int* in_sizes, int n_in,
                              void* d_out, int out_size)
{
    const float* o       = (const float*)d_in[0];
    const float* d       = (const float*)d_in[1];
    const float* tnear   = (const float*)d_in[2];
    const float* tfar    = (const float*)d_in[3];
    const float* noise   = (const float*)d_in[4];
    const float* W1      = (const float*)d_in[5];
    const float* b1      = (const float*)d_in[6];
    const float* w_sigma = (const float*)d_in[7];
    const float* W_rgb   = (const float*)d_in[8];
    float* out = (float*)d_out;

    const int N = in_sizes[2];  // tnear element count
    const int threads = 128;
    const int blocks = (N + threads - 1) / threads;
    nerf_render_kernel<<<blocks, threads>>>(o, d, tnear, tfar, noise,
                                            W1, b1, w_sigma, W_rgb, out, N);
}

// round 12
// speedup vs baseline: 1.1748x; 1.1748x over previous
#include <cuda_runtime.h>
#include <math.h>

#define T_SAMPLES 128
#define HID 16
#define HPAIRS (HID / 2)
#define SEGS 4
#define SEG_LEN (T_SAMPLES / SEGS)   // 32
#define RAYS_PER_WARP 8
#define RAYS_PER_BLOCK 32            // 128 threads / 4 segs

typedef unsigned long long u64;

#define LOG2E 1.4426950408889634f

// ---- packed f32x2 helpers (sm_100+; emits FFMA2 in SASS) ----
__device__ __forceinline__ u64 pack2(float lo, float hi) {
    u64 r; asm("mov.b64 %0, {%1,%2};" : "=l"(r) : "f"(lo), "f"(hi)); return r;
}
__device__ __forceinline__ void unpack2(u64 v, float& lo, float& hi) {
    asm("mov.b64 {%0,%1}, %2;" : "=f"(lo), "=f"(hi) : "l"(v));
}
__device__ __forceinline__ u64 fma2(u64 a, u64 b, u64 c) {
    u64 r; asm("fma.rn.f32x2 %0, %1, %2, %3;" : "=l"(r) : "l"(a), "l"(b), "l"(c));
    return r;
}
__device__ __forceinline__ u64 relu2(u64 v) {
    float lo, hi;
    unpack2(v, lo, hi);
    lo = fmaxf(lo, 0.0f);
    hi = fmaxf(hi, 0.0f);
    return pack2(lo, hi);
}
__device__ __forceinline__ float ex2(float x) {
    float r; asm("ex2.approx.f32 %0, %1;" : "=f"(r) : "f"(x)); return r;
}
__device__ __forceinline__ float lg2(float x) {
    float r; asm("lg2.approx.f32 %0, %1;" : "=f"(r) : "f"(x)); return r;
}
__device__ __forceinline__ float rcp(float x) {
    float r; asm("rcp.approx.f32 %0, %1;" : "=f"(r) : "f"(x)); return r;
}

__global__ void __launch_bounds__(128, 3)
nerf_render_kernel(const float* __restrict__ o,
                   const float* __restrict__ d,
                   const float* __restrict__ tnear,
                   const float* __restrict__ tfar,
                   const float* __restrict__ noise,
                   const float* __restrict__ W1,      // (3,16)
                   const float* __restrict__ b1,      // (16)
                   const float* __restrict__ w_sigma, // (16,1)
                   const float* __restrict__ W_rgb,   // (16,3)
                   float* __restrict__ out,           // (N,5)
                   int N)
{
    const int tid   = threadIdx.x;
    const int warp  = tid >> 5;
    const int lane  = tid & 31;
    const int seg   = lane >> 3;          // 0..3: which T-segment this lane owns
    const int rlane = lane & 7;           // 0..7: which ray within the warp

    const int ray = blockIdx.x * RAYS_PER_BLOCK + warp * RAYS_PER_WARP + rlane;
    const bool valid = (ray < N);
    const int r = valid ? ray : (N - 1);

    // ---- per-ray geometry (lanes sharing a ray load the same addresses: broadcast) ----
    const float ox = o[3 * r + 0], oy = o[3 * r + 1], oz = o[3 * r + 2];
    const float dx = d[3 * r + 0], dy = d[3 * r + 1], dz = d[3 * r + 2];
    const float dn = sqrtf(dx * dx + dy * dy + dz * dz);
    const float tn = tnear[r];
    const float tf = tfar[r];
    const float step = (tf - tn) * (1.0f / (float)T_SAMPLES);

    // ---- fold ray into layer-1: pre_j(t) = A_j + t * B_j ----
    u64 Ap[HPAIRS], Bp[HPAIRS];
    u64 ws2[HPAIRS], wr0_2[HPAIRS], wr1_2[HPAIRS], wr2_2[HPAIRS];
#pragma unroll
    for (int p = 0; p < HPAIRS; p++) {
        const int j = 2 * p;
        const float w1x0 = __ldg(&W1[0 * HID + j]), w1x1 = __ldg(&W1[0 * HID + j + 1]);
        const float w1y0 = __ldg(&W1[1 * HID + j]), w1y1 = __ldg(&W1[1 * HID + j + 1]);
        const float w1z0 = __ldg(&W1[2 * HID + j]), w1z1 = __ldg(&W1[2 * HID + j + 1]);
        const float A0 = fmaf(ox, w1x0, fmaf(oy, w1y0, fmaf(oz, w1z0, __ldg(&b1[j]))));
        const float A1 = fmaf(ox, w1x1, fmaf(oy, w1y1, fmaf(oz, w1z1, __ldg(&b1[j + 1]))));
        const float B0 = fmaf(dx, w1x0, fmaf(dy, w1y0, dz * w1z0));
        const float B1 = fmaf(dx, w1x1, fmaf(dy, w1y1, dz * w1z1));
        Ap[p] = pack2(A0, A1);
        Bp[p] = pack2(B0, B1);
        ws2[p]   = pack2(__ldg(&w_sigma[j]), __ldg(&w_sigma[j + 1]));
        wr0_2[p] = pack2(__ldg(&W_rgb[j * 3 + 0]), __ldg(&W_rgb[(j + 1) * 3 + 0]));
        wr1_2[p] = pack2(__ldg(&W_rgb[j * 3 + 1]), __ldg(&W_rgb[(j + 1) * 3 + 1]));
        wr2_2[p] = pack2(__ldg(&W_rgb[j * 3 + 2]), __ldg(&W_rgb[(j + 1) * 3 + 2]));
    }

    // ---- segment-local scan over samples [t_base, t_base+SEG_LEN) ----
    const int t_base = seg * SEG_LEN;
    const float u0 = __ldg(&noise[(size_t)t_base * N + r]);
    float ts_prev = fmaf(step, (float)t_base + u0, tn);

    float Ttr = 1.0f;
    float c0 = 0.f, c1 = 0.f, c2 = 0.f, dep = 0.f, alp = 0.f;

#pragma unroll 2
    for (int t0 = t_base + 1; t0 < t_base + SEG_LEN; t0 += 2) {
        // samples a = t0-1 at ts_prev, b = t0 at ts_a; last pair's b-boundary may be tf
        const float ua = __ldg(&noise[(size_t)t0 * N + r]);
        const float ts_a = fmaf(step, (float)t0 + ua, tn);
        float ts_b;
        if (t0 + 1 < T_SAMPLES) {
            const float ub = __ldg(&noise[(size_t)(t0 + 1) * N + r]);
            ts_b = fmaf(step, (float)(t0 + 1) + ub, tn);
        } else {
            ts_b = tf;
        }

        const float nk_a = (ts_prev - ts_a) * dn;
        const float nk_b = (ts_a - ts_b) * dn;

        const u64 tpa = pack2(ts_prev, ts_prev);
        const u64 tpb = pack2(ts_a, ts_a);

        u64 sa = 0ull, a0 = 0ull, a1 = 0ull, a2 = 0ull;
        u64 sb = 0ull, b0 = 0ull, b1v = 0ull, b2 = 0ull;
#pragma unroll
        for (int p = 0; p < HPAIRS; p++) {
            u64 ha = fma2(tpa, Bp[p], Ap[p]);
            u64 hb = fma2(tpb, Bp[p], Ap[p]);
            ha = relu2(ha);
            hb = relu2(hb);
            sa  = fma2(ha, ws2[p],   sa);
            sb  = fma2(hb, ws2[p],   sb);
            a0  = fma2(ha, wr0_2[p], a0);
            b0  = fma2(hb, wr0_2[p], b0);
            a1  = fma2(ha, wr1_2[p], a1);
            b1v = fma2(hb, wr1_2[p], b1v);
            a2  = fma2(ha, wr2_2[p], a2);
            b2  = fma2(hb, wr2_2[p], b2);
        }

        float xl, xh;
        unpack2(sa, xl, xh);  const float accs_a = xl + xh;
        unpack2(sb, xl, xh);  const float accs_b = xl + xh;
        unpack2(a0, xl, xh);  const float r0a = xl + xh;
        unpack2(a1, xl, xh);  const float r1a = xl + xh;
        unpack2(a2, xl, xh);  const float r2a = xl + xh;
        unpack2(b0, xl, xh);  const float r0b = xl + xh;
        unpack2(b1v, xl, xh); const float r1b = xl + xh;
        unpack2(b2, xl, xh);  const float r2b = xl + xh;

        // fused softplus+exp:  e = 2^( -k * log2(1 + 2^(a*log2e)) )
        const float la = lg2(1.0f + ex2(accs_a * LOG2E));
        const float lb = lg2(1.0f + ex2(accs_b * LOG2E));
        const float ea = ex2(nk_a * la);
        const float eb = ex2(nk_b * lb);

        const float s0a = rcp(1.0f + ex2(-r0a * LOG2E));
        const float s1a = rcp(1.0f + ex2(-r1a * LOG2E));
        const float s2a = rcp(1.0f + ex2(-r2a * LOG2E));
        const float s0b = rcp(1.0f + ex2(-r0b * LOG2E));
        const float s1b = rcp(1.0f + ex2(-r1b * LOG2E));
        const float s2b = rcp(1.0f + ex2(-r2b * LOG2E));

        const float wa = Ttr * (1.0f - ea);
        const float Ttr_a = Ttr * ea;
        const float wb = Ttr_a * (1.0f - eb);
        Ttr = Ttr_a * eb;

        c0  = fmaf(wa, s0a, fmaf(wb, s0b, c0));
        c1  = fmaf(wa, s1a, fmaf(wb, s1b, c1));
        c2  = fmaf(wa, s2a, fmaf(wb, s2b, c2));
        dep = fmaf(wa, ts_prev, fmaf(wb, ts_a, dep));
        alp += wa + wb;

        ts_prev = ts_b;
    }

    // ---- segmented-scan combine across the 4 segment lanes ----
    // combine(first, second): c += Ttr_first * c_second ; Ttr *= Ttr_second
    const unsigned FULL = 0xFFFFFFFFu;
#pragma unroll
    for (int m = 8; m <= 16; m <<= 1) {
        const float pc0 = __shfl_xor_sync(FULL, c0,  m);
        const float pc1 = __shfl_xor_sync(FULL, c1,  m);
        const float pc2 = __shfl_xor_sync(FULL, c2,  m);
        const float pdp = __shfl_xor_sync(FULL, dep, m);
        const float pal = __shfl_xor_sync(FULL, alp, m);
        const float pT  = __shfl_xor_sync(FULL, Ttr, m);
        const bool i_am_first = ((lane & m) == 0);
        if (i_am_first) {
            c0  = fmaf(Ttr, pc0, c0);
            c1  = fmaf(Ttr, pc1, c1);
            c2  = fmaf(Ttr, pc2, c2);
            dep = fmaf(Ttr, pdp, dep);
            alp = fmaf(Ttr, pal, alp);
        } else {
            c0  = fmaf(pT, c0,  pc0);
            c1  = fmaf(pT, c1,  pc1);
            c2  = fmaf(pT, c2,  pc2);
            dep = fmaf(pT, dep, pdp);
            alp = fmaf(pT, alp, pal);
        }
        Ttr *= pT;
    }

    if (seg == 0 && valid) {
        out[5 * r + 0] = c0;
        out[5 * r + 1] = c1;
        out[5 * r + 2] = c2;
        out[5 * r + 3] = dep;
        out[5 * r + 4] = alp;
    }
}

extern "C" void kernel_launch(void* const* d_in, const int* in_sizes, int n_in,
                              void* d_out, int out_size)
{
    const float* o       = (const float*)d_in[0];
    const float* d       = (const float*)d_in[1];
    const float* tnear   = (const float*)d_in[2];
    const float* tfar    = (const float*)d_in[3];
    const float* noise   = (const float*)d_in[4];
    const float* W1      = (const float*)d_in[5];
    const float* b1      = (const float*)d_in[6];
    const float* w_sigma = (const float*)d_in[7];
    const float* W_rgb   = (const float*)d_in[8];
    float* out = (float*)d_out;

    const int N = in_sizes[2];  // tnear element count
    const int threads = 128;
    const int blocks = (N + RAYS_PER_BLOCK - 1) / RAYS_PER_BLOCK;
    nerf_render_kernel<<<blocks, threads>>>(o, d, tnear, tfar, noise,
                                            W1, b1, w_sigma, W_rgb, out, N);
}

// round 13
// speedup vs baseline: 1.3076x; 1.1131x over previous
#include <cuda_runtime.h>
#include <math.h>

#define T_SAMPLES 128
#define HID 16
#define HPAIRS (HID / 2)
#define SEGS 4
#define SEG_LEN (T_SAMPLES / SEGS)   // 32
#define RAYS_PER_WARP 8
#define RAYS_PER_BLOCK 32            // 128 threads / 4 segs

typedef unsigned long long u64;

#define LOG2E 1.4426950408889634f

// ---- packed f32x2 helpers (sm_100+; emits FFMA2 in SASS) ----
__device__ __forceinline__ u64 pack2(float lo, float hi) {
    u64 r; asm("mov.b64 %0, {%1,%2};" : "=l"(r) : "f"(lo), "f"(hi)); return r;
}
__device__ __forceinline__ void unpack2(u64 v, float& lo, float& hi) {
    asm("mov.b64 {%0,%1}, %2;" : "=f"(lo), "=f"(hi) : "l"(v));
}
__device__ __forceinline__ u64 fma2(u64 a, u64 b, u64 c) {
    u64 r; asm("fma.rn.f32x2 %0, %1, %2, %3;" : "=l"(r) : "l"(a), "l"(b), "l"(c));
    return r;
}
__device__ __forceinline__ u64 relu2(u64 v) {
    float lo, hi;
    unpack2(v, lo, hi);
    lo = fmaxf(lo, 0.0f);
    hi = fmaxf(hi, 0.0f);
    return pack2(lo, hi);
}
__device__ __forceinline__ float ex2(float x) {
    float r; asm("ex2.approx.f32 %0, %1;" : "=f"(r) : "f"(x)); return r;
}
__device__ __forceinline__ float lg2(float x) {
    float r; asm("lg2.approx.f32 %0, %1;" : "=f"(r) : "f"(x)); return r;
}
__device__ __forceinline__ float tanh_ap(float x) {
    float r; asm("tanh.approx.f32 %0, %1;" : "=f"(r) : "f"(x)); return r;
}

__global__ void __launch_bounds__(128, 3)
nerf_render_kernel(const float* __restrict__ o,
                   const float* __restrict__ d,
                   const float* __restrict__ tnear,
                   const float* __restrict__ tfar,
                   const float* __restrict__ noise,
                   const float* __restrict__ W1,      // (3,16)
                   const float* __restrict__ b1,      // (16)
                   const float* __restrict__ w_sigma, // (16,1)
                   const float* __restrict__ W_rgb,   // (16,3)
                   float* __restrict__ out,           // (N,5)
                   int N)
{
    const int tid   = threadIdx.x;
    const int warp  = tid >> 5;
    const int lane  = tid & 31;
    const int seg   = lane >> 3;          // 0..3: which T-segment this lane owns
    const int rlane = lane & 7;           // 0..7: which ray within the warp

    const int ray = blockIdx.x * RAYS_PER_BLOCK + warp * RAYS_PER_WARP + rlane;
    const bool valid = (ray < N);
    const int r = valid ? ray : (N - 1);

    // ---- per-ray geometry ----
    const float ox = o[3 * r + 0], oy = o[3 * r + 1], oz = o[3 * r + 2];
    const float dx = d[3 * r + 0], dy = d[3 * r + 1], dz = d[3 * r + 2];
    const float dn = sqrtf(dx * dx + dy * dy + dz * dz);
    const float tn = tnear[r];
    const float tf = tfar[r];
    const float step = (tf - tn) * (1.0f / (float)T_SAMPLES);

    // ---- fold ray into layer-1: pre_j(t) = A_j + t * B_j ----
    // W_rgb weights pre-scaled by 0.5 so accumulators produce r/2 for tanh-sigmoid.
    u64 Ap[HPAIRS], Bp[HPAIRS];
    u64 ws2[HPAIRS], wr0_2[HPAIRS], wr1_2[HPAIRS], wr2_2[HPAIRS];
#pragma unroll
    for (int p = 0; p < HPAIRS; p++) {
        const int j = 2 * p;
        const float w1x0 = __ldg(&W1[0 * HID + j]), w1x1 = __ldg(&W1[0 * HID + j + 1]);
        const float w1y0 = __ldg(&W1[1 * HID + j]), w1y1 = __ldg(&W1[1 * HID + j + 1]);
        const float w1z0 = __ldg(&W1[2 * HID + j]), w1z1 = __ldg(&W1[2 * HID + j + 1]);
        const float A0 = fmaf(ox, w1x0, fmaf(oy, w1y0, fmaf(oz, w1z0, __ldg(&b1[j]))));
        const float A1 = fmaf(ox, w1x1, fmaf(oy, w1y1, fmaf(oz, w1z1, __ldg(&b1[j + 1]))));
        const float B0 = fmaf(dx, w1x0, fmaf(dy, w1y0, dz * w1z0));
        const float B1 = fmaf(dx, w1x1, fmaf(dy, w1y1, dz * w1z1));
        Ap[p] = pack2(A0, A1);
        Bp[p] = pack2(B0, B1);
        ws2[p]   = pack2(__ldg(&w_sigma[j]), __ldg(&w_sigma[j + 1]));
        wr0_2[p] = pack2(0.5f * __ldg(&W_rgb[j * 3 + 0]), 0.5f * __ldg(&W_rgb[(j + 1) * 3 + 0]));
        wr1_2[p] = pack2(0.5f * __ldg(&W_rgb[j * 3 + 1]), 0.5f * __ldg(&W_rgb[(j + 1) * 3 + 1]));
        wr2_2[p] = pack2(0.5f * __ldg(&W_rgb[j * 3 + 2]), 0.5f * __ldg(&W_rgb[(j + 1) * 3 + 2]));
    }

    // ---- segment-local scan over samples [t_base, t_base+SEG_LEN) ----
    const int t_base = seg * SEG_LEN;
    const float u0 = __ldg(&noise[(size_t)t_base * N + r]);
    float ts_prev = fmaf(step, (float)t_base + u0, tn);

    float Ttr = 1.0f;
    float c0 = 0.f, c1 = 0.f, c2 = 0.f, dep = 0.f, alp = 0.f;

#pragma unroll 2
    for (int t0 = t_base + 1; t0 < t_base + SEG_LEN; t0 += 2) {
        const float ua = __ldg(&noise[(size_t)t0 * N + r]);
        const float ts_a = fmaf(step, (float)t0 + ua, tn);
        float ts_b;
        if (t0 + 1 < T_SAMPLES) {
            const float ub = __ldg(&noise[(size_t)(t0 + 1) * N + r]);
            ts_b = fmaf(step, (float)(t0 + 1) + ub, tn);
        } else {
            ts_b = tf;
        }

        const float nk_a = (ts_prev - ts_a) * dn;
        const float nk_b = (ts_a - ts_b) * dn;

        const u64 tpa = pack2(ts_prev, ts_prev);
        const u64 tpb = pack2(ts_a, ts_a);

        u64 sa = 0ull, a0 = 0ull, a1 = 0ull, a2 = 0ull;
        u64 sb = 0ull, b0 = 0ull, b1v = 0ull, b2 = 0ull;
#pragma unroll
        for (int p = 0; p < HPAIRS; p++) {
            u64 ha = fma2(tpa, Bp[p], Ap[p]);
            u64 hb = fma2(tpb, Bp[p], Ap[p]);
            ha = relu2(ha);
            hb = relu2(hb);
            sa  = fma2(ha, ws2[p],   sa);
            sb  = fma2(hb, ws2[p],   sb);
            a0  = fma2(ha, wr0_2[p], a0);
            b0  = fma2(hb, wr0_2[p], b0);
            a1  = fma2(ha, wr1_2[p], a1);
            b1v = fma2(hb, wr1_2[p], b1v);
            a2  = fma2(ha, wr2_2[p], a2);
            b2  = fma2(hb, wr2_2[p], b2);
        }

        float xl, xh;
        unpack2(sa, xl, xh);  const float accs_a = xl + xh;
        unpack2(sb, xl, xh);  const float accs_b = xl + xh;
        unpack2(a0, xl, xh);  const float h0a = xl + xh;   // = r0/2
        unpack2(a1, xl, xh);  const float h1a = xl + xh;
        unpack2(a2, xl, xh);  const float h2a = xl + xh;
        unpack2(b0, xl, xh);  const float h0b = xl + xh;
        unpack2(b1v, xl, xh); const float h1b = xl + xh;
        unpack2(b2, xl, xh);  const float h2b = xl + xh;

        // fused softplus+exp:  e = 2^( -k * log2(1 + 2^(a*log2e)) )
        const float la = lg2(1.0f + ex2(accs_a * LOG2E));
        const float lb = lg2(1.0f + ex2(accs_b * LOG2E));
        const float ea = ex2(nk_a * la);
        const float eb = ex2(nk_b * lb);

        // sigmoid(r) = 0.5*tanh(r/2) + 0.5 ; accumulators hold r/2 already
        const float s0a = fmaf(0.5f, tanh_ap(h0a), 0.5f);
        const float s1a = fmaf(0.5f, tanh_ap(h1a), 0.5f);
        const float s2a = fmaf(0.5f, tanh_ap(h2a), 0.5f);
        const float s0b = fmaf(0.5f, tanh_ap(h0b), 0.5f);
        const float s1b = fmaf(0.5f, tanh_ap(h1b), 0.5f);
        const float s2b = fmaf(0.5f, tanh_ap(h2b), 0.5f);

        const float wa = Ttr * (1.0f - ea);
        const float Ttr_a = Ttr * ea;
        const float wb = Ttr_a * (1.0f - eb);
        Ttr = Ttr_a * eb;

        c0  = fmaf(wa, s0a, fmaf(wb, s0b, c0));
        c1  = fmaf(wa, s1a, fmaf(wb, s1b, c1));
        c2  = fmaf(wa, s2a, fmaf(wb, s2b, c2));
        dep = fmaf(wa, ts_prev, fmaf(wb, ts_a, dep));
        alp += wa + wb;

        ts_prev = ts_b;
    }

    // ---- segmented-scan combine across the 4 segment lanes ----
    const unsigned FULL = 0xFFFFFFFFu;
#pragma unroll
    for (int m = 8; m <= 16; m <<= 1) {
        const float pc0 = __shfl_xor_sync(FULL, c0,  m);
        const float pc1 = __shfl_xor_sync(FULL, c1,  m);
        const float pc2 = __shfl_xor_sync(FULL, c2,  m);
        const float pdp = __shfl_xor_sync(FULL, dep, m);
        const float pal = __shfl_xor_sync(FULL, alp, m);
        const float pT  = __shfl_xor_sync(FULL, Ttr, m);
        const bool i_am_first = ((lane & m) == 0);
        if (i_am_first) {
            c0  = fmaf(Ttr, pc0, c0);
            c1  = fmaf(Ttr, pc1, c1);
            c2  = fmaf(Ttr, pc2, c2);
            dep = fmaf(Ttr, pdp, dep);
            alp = fmaf(Ttr, pal, alp);
        } else {
            c0  = fmaf(pT, c0,  pc0);
            c1  = fmaf(pT, c1,  pc1);
            c2  = fmaf(pT, c2,  pc2);
            dep = fmaf(pT, dep, pdp);
            alp = fmaf(pT, alp, pal);
        }
        Ttr *= pT;
    }

    if (seg == 0 && valid) {
        out[5 * r + 0] = c0;
        out[5 * r + 1] = c1;
        out[5 * r + 2] = c2;
        out[5 * r + 3] = dep;
        out[5 * r + 4] = alp;
    }
}

extern "C" void kernel_launch(void* const* d_in, const int* in_sizes, int n_in,
                              void* d_out, int out_size)
{
    const float* o       = (const float*)d_in[0];
    const float* d       = (const float*)d_in[1];
    const float* tnear   = (const float*)d_in[2];
    const float* tfar    = (const float*)d_in[3];
    const float* noise   = (const float*)d_in[4];
    const float* W1      = (const float*)d_in[5];
    const float* b1      = (const float*)d_in[6];
    const float* w_sigma = (const float*)d_in[7];
    const float* W_rgb   = (const float*)d_in[8];
    float* out = (float*)d_out;

    const int N = in_sizes[2];  // tnear element count
    const int threads = 128;
    const int blocks = (N + RAYS_PER_BLOCK - 1) / RAYS_PER_BLOCK;
    nerf_render_kernel<<<blocks, threads>>>(o, d, tnear, tfar, noise,
                                            W1, b1, w_sigma, W_rgb, out, N);
}

// round 14
// speedup vs baseline: 1.3215x; 1.0106x over previous
#include <cuda_runtime.h>
#include <math.h>

#define T_SAMPLES 128
#define HID 16
#define HPAIRS (HID / 2)
#define SEGS 4
#define SEG_LEN (T_SAMPLES / SEGS)   // 32
#define RAYS_PER_WARP 8
#define RAYS_PER_BLOCK 32            // 128 threads / 4 segs

typedef unsigned long long u64;

#define LOG2E 1.4426950408889634f

// ---- packed f32x2 helpers (sm_100+; emits FFMA2 in SASS) ----
__device__ __forceinline__ u64 pack2(float lo, float hi) {
    u64 r; asm("mov.b64 %0, {%1,%2};" : "=l"(r) : "f"(lo), "f"(hi)); return r;
}
__device__ __forceinline__ void unpack2(u64 v, float& lo, float& hi) {
    asm("mov.b64 {%0,%1}, %2;" : "=f"(lo), "=f"(hi) : "l"(v));
}
__device__ __forceinline__ u64 fma2(u64 a, u64 b, u64 c) {
    u64 r; asm("fma.rn.f32x2 %0, %1, %2, %3;" : "=l"(r) : "l"(a), "l"(b), "l"(c));
    return r;
}
__device__ __forceinline__ u64 relu2(u64 v) {
    float lo, hi;
    unpack2(v, lo, hi);
    lo = fmaxf(lo, 0.0f);
    hi = fmaxf(hi, 0.0f);
    return pack2(lo, hi);
}
__device__ __forceinline__ float ex2(float x) {
    float r; asm("ex2.approx.f32 %0, %1;" : "=f"(r) : "f"(x)); return r;
}
__device__ __forceinline__ float lg2(float x) {
    float r; asm("lg2.approx.f32 %0, %1;" : "=f"(r) : "f"(x)); return r;
}
__device__ __forceinline__ float tanh_ap(float x) {
    float r; asm("tanh.approx.f32 %0, %1;" : "=f"(r) : "f"(x)); return r;
}

__global__ void __launch_bounds__(128, 3)
nerf_render_kernel(const float* __restrict__ o,
                   const float* __restrict__ d,
                   const float* __restrict__ tnear,
                   const float* __restrict__ tfar,
                   const float* __restrict__ noise,
                   const float* __restrict__ W1,      // (3,16)
                   const float* __restrict__ b1,      // (16)
                   const float* __restrict__ w_sigma, // (16,1)
                   const float* __restrict__ W_rgb,   // (16,3)
                   float* __restrict__ out,           // (N,5)
                   int N)
{
    const int tid   = threadIdx.x;
    const int warp  = tid >> 5;
    const int lane  = tid & 31;
    const int seg   = lane >> 3;          // 0..3: which T-segment this lane owns
    const int rlane = lane & 7;           // 0..7: which ray within the warp

    const int ray = blockIdx.x * RAYS_PER_BLOCK + warp * RAYS_PER_WARP + rlane;
    const bool valid = (ray < N);
    const int r = valid ? ray : (N - 1);

    // ---- per-ray geometry ----
    const float ox = o[3 * r + 0], oy = o[3 * r + 1], oz = o[3 * r + 2];
    const float dx = d[3 * r + 0], dy = d[3 * r + 1], dz = d[3 * r + 2];
    const float dn = sqrtf(dx * dx + dy * dy + dz * dz);
    const float tn = tnear[r];
    const float tf = tfar[r];
    const float step = (tf - tn) * (1.0f / (float)T_SAMPLES);

    // ---- fold ray into layer-1: pre_j(t) = A_j + t * B_j ----
    // w_sigma pre-scaled by LOG2E (softplus-exp wants accs*log2e);
    // W_rgb pre-scaled by 0.5 (tanh-sigmoid wants r/2).
    u64 Ap[HPAIRS], Bp[HPAIRS];
    u64 ws2[HPAIRS], wr0_2[HPAIRS], wr1_2[HPAIRS], wr2_2[HPAIRS];
#pragma unroll
    for (int p = 0; p < HPAIRS; p++) {
        const int j = 2 * p;
        const float w1x0 = __ldg(&W1[0 * HID + j]), w1x1 = __ldg(&W1[0 * HID + j + 1]);
        const float w1y0 = __ldg(&W1[1 * HID + j]), w1y1 = __ldg(&W1[1 * HID + j + 1]);
        const float w1z0 = __ldg(&W1[2 * HID + j]), w1z1 = __ldg(&W1[2 * HID + j + 1]);
        const float A0 = fmaf(ox, w1x0, fmaf(oy, w1y0, fmaf(oz, w1z0, __ldg(&b1[j]))));
        const float A1 = fmaf(ox, w1x1, fmaf(oy, w1y1, fmaf(oz, w1z1, __ldg(&b1[j + 1]))));
        const float B0 = fmaf(dx, w1x0, fmaf(dy, w1y0, dz * w1z0));
        const float B1 = fmaf(dx, w1x1, fmaf(dy, w1y1, dz * w1z1));
        Ap[p] = pack2(A0, A1);
        Bp[p] = pack2(B0, B1);
        ws2[p]   = pack2(LOG2E * __ldg(&w_sigma[j]), LOG2E * __ldg(&w_sigma[j + 1]));
        wr0_2[p] = pack2(0.5f * __ldg(&W_rgb[j * 3 + 0]), 0.5f * __ldg(&W_rgb[(j + 1) * 3 + 0]));
        wr1_2[p] = pack2(0.5f * __ldg(&W_rgb[j * 3 + 1]), 0.5f * __ldg(&W_rgb[(j + 1) * 3 + 1]));
        wr2_2[p] = pack2(0.5f * __ldg(&W_rgb[j * 3 + 2]), 0.5f * __ldg(&W_rgb[(j + 1) * 3 + 2]));
    }

    // ---- segment-local scan over samples [t_base, t_base+SEG_LEN) ----
    const int t_base = seg * SEG_LEN;
    const float u0 = __ldg(&noise[(size_t)t_base * N + r]);
    float ts_prev = fmaf(step, (float)t_base + u0, tn);

    float Ttr = 1.0f;
    float c0 = 0.f, c1 = 0.f, c2 = 0.f, dep = 0.f, alp = 0.f;

#pragma unroll 4
    for (int t0 = t_base + 1; t0 < t_base + SEG_LEN; t0 += 2) {
        const float ua = __ldg(&noise[(size_t)t0 * N + r]);
        const float ts_a = fmaf(step, (float)t0 + ua, tn);
        float ts_b;
        if (t0 + 1 < T_SAMPLES) {
            const float ub = __ldg(&noise[(size_t)(t0 + 1) * N + r]);
            ts_b = fmaf(step, (float)(t0 + 1) + ub, tn);
        } else {
            ts_b = tf;
        }

        const float nk_a = (ts_prev - ts_a) * dn;
        const float nk_b = (ts_a - ts_b) * dn;

        const u64 tpa = pack2(ts_prev, ts_prev);
        const u64 tpb = pack2(ts_a, ts_a);

        u64 sa = 0ull, a0 = 0ull, a1 = 0ull, a2 = 0ull;
        u64 sb = 0ull, b0 = 0ull, b1v = 0ull, b2 = 0ull;
#pragma unroll
        for (int p = 0; p < HPAIRS; p++) {
            u64 ha = fma2(tpa, Bp[p], Ap[p]);
            u64 hb = fma2(tpb, Bp[p], Ap[p]);
            ha = relu2(ha);
            hb = relu2(hb);
            sa  = fma2(ha, ws2[p],   sa);
            sb  = fma2(hb, ws2[p],   sb);
            a0  = fma2(ha, wr0_2[p], a0);
            b0  = fma2(hb, wr0_2[p], b0);
            a1  = fma2(ha, wr1_2[p], a1);
            b1v = fma2(hb, wr1_2[p], b1v);
            a2  = fma2(ha, wr2_2[p], a2);
            b2  = fma2(hb, wr2_2[p], b2);
        }

        float xl, xh;
        unpack2(sa, xl, xh);  const float la_in = xl + xh;   // = accs_a * log2e
        unpack2(sb, xl, xh);  const float lb_in = xl + xh;
        unpack2(a0, xl, xh);  const float h0a = xl + xh;     // = r0/2
        unpack2(a1, xl, xh);  const float h1a = xl + xh;
        unpack2(a2, xl, xh);  const float h2a = xl + xh;
        unpack2(b0, xl, xh);  const float h0b = xl + xh;
        unpack2(b1v, xl, xh); const float h1b = xl + xh;
        unpack2(b2, xl, xh);  const float h2b = xl + xh;

        // fused softplus+exp:  e = 2^( -k * log2(1 + 2^(accs*log2e)) )
        const float la = lg2(1.0f + ex2(la_in));
        const float lb = lg2(1.0f + ex2(lb_in));
        const float ea = ex2(nk_a * la);
        const float eb = ex2(nk_b * lb);

        // sigmoid(r) = 0.5*tanh(r/2) + 0.5
        const float s0a = fmaf(0.5f, tanh_ap(h0a), 0.5f);
        const float s1a = fmaf(0.5f, tanh_ap(h1a), 0.5f);
        const float s2a = fmaf(0.5f, tanh_ap(h2a), 0.5f);
        const float s0b = fmaf(0.5f, tanh_ap(h0b), 0.5f);
        const float s1b = fmaf(0.5f, tanh_ap(h1b), 0.5f);
        const float s2b = fmaf(0.5f, tanh_ap(h2b), 0.5f);

        const float wa = Ttr * (1.0f - ea);
        const float Ttr_a = Ttr * ea;
        const float wb = Ttr_a * (1.0f - eb);
        Ttr = Ttr_a * eb;

        c0  = fmaf(wa, s0a, fmaf(wb, s0b, c0));
        c1  = fmaf(wa, s1a, fmaf(wb, s1b, c1));
        c2  = fmaf(wa, s2a, fmaf(wb, s2b, c2));
        dep = fmaf(wa, ts_prev, fmaf(wb, ts_a, dep));
        alp += wa + wb;

        ts_prev = ts_b;
    }

    // ---- segmented-scan combine across the 4 segment lanes ----
    const unsigned FULL = 0xFFFFFFFFu;
#pragma unroll
    for (int m = 8; m <= 16; m <<= 1) {
        const float pc0 = __shfl_xor_sync(FULL, c0,  m);
        const float pc1 = __shfl_xor_sync(FULL, c1,  m);
        const float pc2 = __shfl_xor_sync(FULL, c2,  m);
        const float pdp = __shfl_xor_sync(FULL, dep, m);
        const float pal = __shfl_xor_sync(FULL, alp, m);
        const float pT  = __shfl_xor_sync(FULL, Ttr, m);
        const bool i_am_first = ((lane & m) == 0);
        if (i_am_first) {
            c0  = fmaf(Ttr, pc0, c0);
            c1  = fmaf(Ttr, pc1, c1);
            c2  = fmaf(Ttr, pc2, c2);
            dep = fmaf(Ttr, pdp, dep);
            alp = fmaf(Ttr, pal, alp);
        } else {
            c0  = fmaf(pT, c0,  pc0);
            c1  = fmaf(pT, c1,  pc1);
            c2  = fmaf(pT, c2,  pc2);
            dep = fmaf(pT, dep, pdp);
            alp = fmaf(pT, alp, pal);
        }
        Ttr *= pT;
    }

    if (seg == 0 && valid) {
        out[5 * r + 0] = c0;
        out[5 * r + 1] = c1;
        out[5 * r + 2] = c2;
        out[5 * r + 3] = dep;
        out[5 * r + 4] = alp;
    }
}

extern "C" void kernel_launch(void* const* d_in, const int* in_sizes, int n_in,
                              void* d_out, int out_size)
{
    const float* o       = (const float*)d_in[0];
    const float* d       = (const float*)d_in[1];
    const float* tnear   = (const float*)d_in[2];
    const float* tfar    = (const float*)d_in[3];
    const float* noise   = (const float*)d_in[4];
    const float* W1      = (const float*)d_in[5];
    const float* b1      = (const float*)d_in[6];
    const float* w_sigma = (const float*)d_in[7];
    const float* W_rgb   = (const float*)d_in[8];
    float* out = (float*)d_out;

    const int N = in_sizes[2];  // tnear element count
    const int threads = 128;
    const int blocks = (N + RAYS_PER_BLOCK - 1) / RAYS_PER_BLOCK;
    nerf_render_kernel<<<blocks, threads>>>(o, d, tnear, tfar, noise,
                                            W1, b1, w_sigma, W_rgb, out, N);
}